// round 1
// baseline (speedup 1.0000x reference)
#include <cuda_runtime.h>
#include <math.h>

// Problem constants
#define Bc 32
#define Sc 1024
#define Ec 256
#define Hc 256
#define NCTA 128      // 64 CTAs per direction, 4 hidden units each
#define TPB 256

// Output section offsets (floats)
#define OUT_C 16777216UL          // S*B*2H
#define OUT_S 33554432UL          // 2 * S*B*2H

// SMEM layout (float offsets)
#define OFF_WA   0        // [16 cols][772]   z-projection weights (x|h|s stacked on k)
#define OFF_WB   12352    // [8 cols][516]    r-projection weights (x|h stacked on k)
#define OFF_BA   16480    // [16]
#define OFF_BB   16496    // [8]
#define OFF_SIN  16512    // [32 b][772]      staged x(0:256) h(256:512) s(512:768)
#define OFF_PRED 41216    // [8 warps][520]   k-split partials
#define OFF_ZBUF 45376    // [512]
#define OFF_CLOC 45888    // [4 jj][32 b]     cell state (CTA-local, persistent)
#define OFF_SLOC 46016    // [8 c][32 b]      shared state (CTA-local, persistent)
#define OFF_HTMP 46272    // [4 jj][32 b]
#define OFF_MASK 46400    // [32]
#define SMEM_FLOATS 46432
#define SMEM_BYTES (SMEM_FLOATS * 4)

// Global scratch (cross-CTA communication). h is double-buffered by step parity.
__device__ float g_h[4 * Bc * Hc];   // [parity][dir][b][j]
__device__ float g_s[4 * Bc * Hc];   // [dir][share][b][j]
__device__ unsigned int g_bar;

__global__ void init_kernel() {
    int tid = blockIdx.x * blockDim.x + threadIdx.x;
    int stride = gridDim.x * blockDim.x;
    for (int i = tid; i < 4 * Bc * Hc; i += stride) { g_h[i] = 0.0f; g_s[i] = 0.0f; }
    if (tid == 0) g_bar = 0u;
}

__device__ __forceinline__ float sigf(float x) { return 1.0f / (1.0f + expf(-x)); }

__device__ __forceinline__ void grid_barrier(unsigned target) {
    __threadfence();          // release: publish this block's global stores
    __syncthreads();
    if (threadIdx.x == 0) {
        atomicAdd(&g_bar, 1u);
        volatile unsigned int* p = &g_bar;
        while (*p < target) { }
        __threadfence();      // acquire
    }
    __syncthreads();
}

__global__ void __launch_bounds__(TPB, 1) bislstm_kernel(
    const float* __restrict__ inputs, const float* __restrict__ mask,
    const float* __restrict__ Wx,   const float* __restrict__ Wh,
    const float* __restrict__ Ws,   const float* __restrict__ bz,
    const float* __restrict__ Wrx,  const float* __restrict__ Wrh,
    const float* __restrict__ br,
    const float* __restrict__ Wx_r, const float* __restrict__ Wh_r,
    const float* __restrict__ Ws_r, const float* __restrict__ bz_r,
    const float* __restrict__ Wrx_r,const float* __restrict__ Wrh_r,
    const float* __restrict__ br_r,
    const int* __restrict__ idx_ptr, float* __restrict__ out)
{
    extern __shared__ float sm[];
    const int tid  = threadIdx.x;
    const int warp = tid >> 5;
    const int lane = tid & 31;
    const int cta  = blockIdx.x;
    const int dir  = cta >> 6;           // 0 = fwd, 1 = rev
    const int cid  = cta & 63;
    const int jbase = cid * 4;           // this CTA's 4 hidden units
    const int idxv = *idx_ptr;

    const float* pWx  = dir ? Wx_r  : Wx;
    const float* pWh  = dir ? Wh_r  : Wh;
    const float* pWs  = dir ? Ws_r  : Ws;
    const float* pB   = dir ? bz_r  : bz;
    const float* pWrx = dir ? Wrx_r : Wrx;
    const float* pWrh = dir ? Wrh_r : Wrh;
    const float* pBr  = dir ? br_r  : br;

    // ---- Load weight slices into SMEM (once) ----
    // WA: [c][k], c = gate*4 + jj, k in [0,768) = x|h|s
    for (int i = tid; i < 16 * 768; i += TPB) {
        int k = i >> 4, c = i & 15;
        int gate = c >> 2, jj = c & 3;
        int gcol = gate * Hc + jbase + jj;
        float v;
        if (k < 256)      v = pWx[(size_t)k * (4 * Hc) + gcol];
        else if (k < 512) v = pWh[(size_t)(k - 256) * (4 * Hc) + gcol];
        else              v = pWs[(size_t)(k - 512) * (4 * Hc) + gcol];
        sm[OFF_WA + c * 772 + k] = v;
    }
    // WB: [c][k], c = share*4 + jj, k in [0,512) = x|h
    for (int i = tid; i < 8 * 512; i += TPB) {
        int k = i >> 3, c = i & 7;
        int kk = c >> 2, jj = c & 3;
        int j = jbase + jj;
        float v;
        if (k < 256) v = pWrx[(size_t)kk * Ec * Hc + (size_t)k * Hc + j];
        else         v = pWrh[(size_t)kk * Hc * Hc + (size_t)(k - 256) * Hc + j];
        sm[OFF_WB + c * 516 + k] = v;
    }
    if (tid < 16) {
        int gate = tid >> 2, jj = tid & 3;
        sm[OFF_BA + tid] = pB[gate * Hc + jbase + jj];
    }
    if (tid < 8) {
        int kk = tid >> 2, jj = tid & 3;
        sm[OFF_BB + tid] = pBr[kk * Hc + jbase + jj];
    }
    if (tid < 128) sm[OFF_CLOC + tid] = 0.0f;
    sm[OFF_SLOC + tid] = 0.0f;
    __syncthreads();

    unsigned bar_target = 0;

    for (int n = 0; n < Sc; ++n) {
        const int t = dir ? (Sc - 1 - n) : n;
        const int prevpar = (n & 1) ^ 1;
        const int curpar  = n & 1;

        // ===== Phase A staging: x, h_prev, s_prev[idx], mask =====
        for (int i = tid; i < 2048; i += TPB) {
            int b = i >> 6, k4 = i & 63;
            float4 v = *reinterpret_cast<const float4*>(
                inputs + ((size_t)b * Sc + t) * Ec + k4 * 4);
            *reinterpret_cast<float4*>(&sm[OFF_SIN + b * 772 + k4 * 4]) = v;
        }
        {
            const float* hsrc = g_h + (size_t)(prevpar * 2 + dir) * (Bc * Hc);
            for (int i = tid; i < 2048; i += TPB) {
                int b = i >> 6, k4 = i & 63;
                float4 v = __ldcg(reinterpret_cast<const float4*>(hsrc + b * 256 + k4 * 4));
                *reinterpret_cast<float4*>(&sm[OFF_SIN + b * 772 + 256 + k4 * 4]) = v;
            }
            const float* ssrc = g_s + (size_t)(dir * 2 + idxv) * (Bc * Hc);
            for (int i = tid; i < 2048; i += TPB) {
                int b = i >> 6, k4 = i & 63;
                float4 v = __ldcg(reinterpret_cast<const float4*>(ssrc + b * 256 + k4 * 4));
                *reinterpret_cast<float4*>(&sm[OFF_SIN + b * 772 + 512 + k4 * 4]) = v;
            }
        }
        if (tid < 32) sm[OFF_MASK + tid] = mask[(size_t)tid * Sc + t];
        __syncthreads();

        // ===== Phase A compute: z = [x|h|s] . WA  (warp k-split, 96 k per warp) =====
        {
            float acc[16];
            #pragma unroll
            for (int c = 0; c < 16; ++c) acc[c] = 0.0f;
            const int k0 = warp * 96;
            const float* inb = &sm[OFF_SIN + lane * 772 + k0];
            const float* wb  = &sm[OFF_WA + k0];
            #pragma unroll 2
            for (int kb = 0; kb < 24; ++kb) {
                float4 xv = *reinterpret_cast<const float4*>(inb + kb * 4);
                #pragma unroll
                for (int c = 0; c < 16; ++c) {
                    float4 wv = *reinterpret_cast<const float4*>(wb + c * 772 + kb * 4);
                    acc[c] = fmaf(xv.x, wv.x, fmaf(xv.y, wv.y,
                             fmaf(xv.z, wv.z, fmaf(xv.w, wv.w, acc[c]))));
                }
            }
            #pragma unroll
            for (int c = 0; c < 16; ++c)
                sm[OFF_PRED + warp * 520 + c * 32 + lane] = acc[c];
        }
        __syncthreads();
        // reduce partials -> z
        for (int o = tid; o < 512; o += TPB) {
            float z = sm[OFF_BA + (o >> 5)];
            #pragma unroll
            for (int w = 0; w < 8; ++w) z += sm[OFF_PRED + w * 520 + o];
            sm[OFF_ZBUF + o] = z;
        }
        __syncthreads();
        // gates + mask blend
        if (tid < 128) {
            const int jj = tid >> 5, b = tid & 31;
            const float zi = sm[OFF_ZBUF + (jj     ) * 32 + b];
            const float zf = sm[OFF_ZBUF + (jj +  4) * 32 + b];
            const float zg = sm[OFF_ZBUF + (jj +  8) * 32 + b];
            const float zo = sm[OFF_ZBUF + (jj + 12) * 32 + b];
            const float cold = sm[OFF_CLOC + tid];
            const float hold = sm[OFF_SIN + b * 772 + 256 + jbase + jj];
            const float m    = sm[OFF_MASK + b];
            const float cn = sigf(zf) * cold + sigf(zi) * tanhf(zg);
            const float hn = sigf(zo) * tanhf(cn);
            const float h = m * hn + (1.0f - m) * hold;
            const float c = m * cn + (1.0f - m) * cold;
            sm[OFF_CLOC + tid] = c;
            sm[OFF_HTMP + tid] = h;
        }
        __syncthreads();
        // publish h, write h/c outputs
        if (tid < 32) {
            const int b = tid;
            float4 hv = make_float4(sm[OFF_HTMP + b],      sm[OFF_HTMP + 32 + b],
                                    sm[OFF_HTMP + 64 + b], sm[OFF_HTMP + 96 + b]);
            float4 cv = make_float4(sm[OFF_CLOC + b],      sm[OFF_CLOC + 32 + b],
                                    sm[OFF_CLOC + 64 + b], sm[OFF_CLOC + 96 + b]);
            float* hp = g_h + (size_t)(curpar * 2 + dir) * (Bc * Hc) + b * 256 + jbase;
            *reinterpret_cast<float4*>(hp) = hv;
            size_t ob = (size_t)t * (Bc * 512) + (size_t)b * 512 + dir * 256 + jbase;
            *reinterpret_cast<float4*>(out + ob) = hv;
            *reinterpret_cast<float4*>(out + OUT_C + ob) = cv;
        }
        bar_target += NCTA;
        grid_barrier(bar_target);

        // ===== Phase B staging: h_new over h segment =====
        {
            const float* hsrc = g_h + (size_t)(curpar * 2 + dir) * (Bc * Hc);
            for (int i = tid; i < 2048; i += TPB) {
                int b = i >> 6, k4 = i & 63;
                float4 v = __ldcg(reinterpret_cast<const float4*>(hsrc + b * 256 + k4 * 4));
                *reinterpret_cast<float4*>(&sm[OFF_SIN + b * 772 + 256 + k4 * 4]) = v;
            }
        }
        __syncthreads();

        // ===== Phase B compute: r = sig([x|h_new] . WB + br), s update =====
        {
            float acc[8];
            #pragma unroll
            for (int c = 0; c < 8; ++c) acc[c] = 0.0f;
            const int k0 = warp * 64;
            const float* inb = &sm[OFF_SIN + lane * 772 + k0];
            const float* wb  = &sm[OFF_WB + k0];
            #pragma unroll 2
            for (int kb = 0; kb < 16; ++kb) {
                float4 xv = *reinterpret_cast<const float4*>(inb + kb * 4);
                #pragma unroll
                for (int c = 0; c < 8; ++c) {
                    float4 wv = *reinterpret_cast<const float4*>(wb + c * 516 + kb * 4);
                    acc[c] = fmaf(xv.x, wv.x, fmaf(xv.y, wv.y,
                             fmaf(xv.z, wv.z, fmaf(xv.w, wv.w, acc[c]))));
                }
            }
            #pragma unroll
            for (int c = 0; c < 8; ++c)
                sm[OFF_PRED + warp * 520 + c * 32 + lane] = acc[c];
        }
        __syncthreads();
        {
            const int o = tid;                 // 256 outputs
            const int c = o >> 5, b = o & 31;
            const int jj = c & 3;
            float z = sm[OFF_BB + c];
            #pragma unroll
            for (int w = 0; w < 8; ++w) z += sm[OFF_PRED + w * 520 + o];
            const float r    = sigf(z);
            const float sold = sm[OFF_SLOC + o];
            const float cc   = sm[OFF_CLOC + jj * 32 + b];
            const float m    = sm[OFF_MASK + b];
            const float sn   = r * sold + (1.0f - r) * cc;
            sm[OFF_SLOC + o] = m * sn + (1.0f - m) * sold;
        }
        __syncthreads();
        if (tid < 64) {
            const int kk = tid >> 5, b = tid & 31;
            const int base = (kk * 4) * 32 + b;
            float4 sv = make_float4(sm[OFF_SLOC + base],      sm[OFF_SLOC + base + 32],
                                    sm[OFF_SLOC + base + 64], sm[OFF_SLOC + base + 96]);
            *reinterpret_cast<float4*>(
                g_s + (size_t)(dir * 2 + kk) * (Bc * Hc) + b * 256 + jbase) = sv;
            size_t ob = (size_t)kk * ((size_t)Sc * Bc * 512)
                      + (size_t)t * (Bc * 512) + (size_t)b * 512 + dir * 256 + jbase;
            *reinterpret_cast<float4*>(out + OUT_S + ob) = sv;
        }
        bar_target += NCTA;
        grid_barrier(bar_target);
    }
}

extern "C" void kernel_launch(void* const* d_in, const int* in_sizes, int n_in,
                              void* d_out, int out_size) {
    (void)in_sizes; (void)n_in; (void)out_size;
    cudaFuncSetAttribute(bislstm_kernel,
                         cudaFuncAttributeMaxDynamicSharedMemorySize, SMEM_BYTES);
    init_kernel<<<64, 256>>>();
    bislstm_kernel<<<NCTA, TPB, SMEM_BYTES>>>(
        (const float*)d_in[0],  (const float*)d_in[1],
        (const float*)d_in[2],  (const float*)d_in[3],
        (const float*)d_in[4],  (const float*)d_in[5],
        (const float*)d_in[6],  (const float*)d_in[7],
        (const float*)d_in[8],
        (const float*)d_in[9],  (const float*)d_in[10],
        (const float*)d_in[11], (const float*)d_in[12],
        (const float*)d_in[13], (const float*)d_in[14],
        (const float*)d_in[15],
        (const int*)d_in[16],   (float*)d_out);
}